// round 1
// baseline (speedup 1.0000x reference)
#include <cuda_runtime.h>

typedef unsigned long long ull;

#define BN 128   // n rows per block
#define BM 64    // m cols per block
#define TN 8     // n per thread
#define TM 4     // m per thread
#define DD 64    // feature dim
#define DP 32    // d pairs (DD/2)
#define THREADS 256

__device__ __forceinline__ ull pack2(float a, float b) {
    ull r;
    asm("mov.b64 %0, {%1, %2};" : "=l"(r) : "f"(a), "f"(b));
    return r;
}

// acc += |x + wneg|  elementwise on packed f32x2 (wneg = -w)
__device__ __forceinline__ void l1acc(ull &acc, ull x, ull wn) {
    ull t;
    asm("add.rn.f32x2 %0, %1, %2;" : "=l"(t) : "l"(x), "l"(wn));
    t &= 0x7FFFFFFF7FFFFFFFULL;   // abs on both halves -> 2x LOP3 (ALU pipe)
    asm("add.rn.f32x2 %0, %0, %1;" : "+l"(acc) : "l"(t));
}

__global__ __launch_bounds__(THREADS, 2)
void cdist_l1_kernel(const float* __restrict__ x,
                     const float* __restrict__ w,
                     float* __restrict__ out,
                     int Mtot) {
    // packed d-pair layout: [dpair][row] ; 32KB + 16KB = 48KB static
    __shared__ ull xs[DP][BN];
    __shared__ ull ws[DP][BM];

    const int tid = threadIdx.x;
    const int n0 = blockIdx.y * BN;
    const int m0 = blockIdx.x * BM;

    // ---- load x tile: BN x DD floats = 2048 float4, 8 per thread ----
    // n-major thread mapping so STS.64 is conflict-free (global reads strided,
    // 2x sector waste, one-time & L2-resident)
    {
        const float4* xg = (const float4*)(x + (size_t)n0 * DD);
        #pragma unroll
        for (int i = 0; i < (BN * DD / 4) / THREADS; i++) {   // 8
            int idx = tid + i * THREADS;
            int n  = idx & (BN - 1);
            int c4 = idx >> 7;            // 0..15, float4 index within row
            float4 v = xg[n * (DD / 4) + c4];
            xs[c4 * 2    ][n] = pack2(v.x, v.y);
            xs[c4 * 2 + 1][n] = pack2(v.z, v.w);
        }
    }
    // ---- load w tile negated: BM x DD = 1024 float4, 4 per thread ----
    {
        const float4* wg = (const float4*)(w + (size_t)m0 * DD);
        #pragma unroll
        for (int i = 0; i < (BM * DD / 4) / THREADS; i++) {   // 4
            int idx = tid + i * THREADS;
            int m  = idx & (BM - 1);
            int c4 = idx >> 6;            // 0..15
            float4 v = wg[m * (DD / 4) + c4];
            ws[c4 * 2    ][m] = pack2(-v.x, -v.y);
            ws[c4 * 2 + 1][m] = pack2(-v.z, -v.w);
        }
    }
    __syncthreads();

    const int tx = tid & 15;   // m group: thread's m values are tx + j*16
    const int ty = tid >> 4;   // n group: thread's n values are ty*8 + i

    ull acc[TN][TM];
    #pragma unroll
    for (int i = 0; i < TN; i++)
        #pragma unroll
        for (int j = 0; j < TM; j++) acc[i][j] = 0ULL;

    #pragma unroll 2
    for (int dp = 0; dp < DP; dp++) {
        ull xr[TN], wr[TM];
        #pragma unroll
        for (int i = 0; i < TN; i++) xr[i] = xs[dp][ty * TN + i];   // broadcast across tx
        #pragma unroll
        for (int j = 0; j < TM; j++) wr[j] = ws[dp][j * 16 + tx];   // conflict-free
        #pragma unroll
        for (int i = 0; i < TN; i++)
            #pragma unroll
            for (int j = 0; j < TM; j++)
                l1acc(acc[i][j], xr[i], wr[j]);
    }

    // ---- epilogue: out[n][m] = -(lo + hi) ----
    #pragma unroll
    for (int i = 0; i < TN; i++) {
        const size_t nrow = (size_t)(n0 + ty * TN + i) * (size_t)Mtot;
        #pragma unroll
        for (int j = 0; j < TM; j++) {
            float lo, hi;
            asm("mov.b64 {%0, %1}, %2;" : "=f"(lo), "=f"(hi) : "l"(acc[i][j]));
            out[nrow + m0 + j * 16 + tx] = -(lo + hi);
        }
    }
}

extern "C" void kernel_launch(void* const* d_in, const int* in_sizes, int n_in,
                              void* d_out, int out_size) {
    const float* x = (const float*)d_in[0];   // [N, 64] fp32
    const float* w = (const float*)d_in[1];   // [M, 64] fp32
    float* out = (float*)d_out;               // [N, M] fp32

    const int N = in_sizes[0] / DD;   // 8192
    const int M = in_sizes[1] / DD;   // 1024

    dim3 grid(M / BM, N / BN);        // (16, 64)
    cdist_l1_kernel<<<grid, THREADS>>>(x, w, out, M);
}

// round 2
// speedup vs baseline: 1.0377x; 1.0377x over previous
#include <cuda_runtime.h>

typedef unsigned long long ull;

#define BN 64    // n rows per block
#define BM 64    // m cols per block
#define TN 4     // n per thread
#define TM 4     // m per thread
#define DD 64    // feature dim
#define DP 32    // d pairs (DD/2)
#define THREADS 256

__device__ __forceinline__ ull pack2(float a, float b) {
    ull r;
    asm("mov.b64 %0, {%1, %2};" : "=l"(r) : "f"(a), "f"(b));
    return r;
}

// acc += |x + wneg|  elementwise on packed f32x2 (wneg = -w)
// 2 FADD2 (fma pipe) + 2 LOP3 (alu pipe) per call -> 1 fma + 1 alu issue per element
__device__ __forceinline__ void l1acc(ull &acc, ull x, ull wn) {
    ull t;
    asm("add.rn.f32x2 %0, %1, %2;" : "=l"(t) : "l"(x), "l"(wn));
    t &= 0x7FFFFFFF7FFFFFFFULL;   // abs on both halves
    asm("add.rn.f32x2 %0, %0, %1;" : "+l"(acc) : "l"(t));
}

__global__ __launch_bounds__(THREADS, 4)
void cdist_l1_kernel(const float* __restrict__ x,
                     const float* __restrict__ w,
                     float* __restrict__ out,
                     int Mtot) {
    // packed d-pair layout: [dpair][row] ; 16KB + 16KB = 32KB static
    __shared__ ull xs[DP][BN];
    __shared__ ull ws[DP][BM];

    const int tid = threadIdx.x;
    const int n0 = blockIdx.y * BN;
    const int m0 = blockIdx.x * BM;

    // ---- load x tile: BN x DD floats = 1024 float4, 4 per thread ----
    // n-major thread mapping -> conflict-free STS.64 (global reads strided but
    // one-time and L2-resident)
    {
        const float4* xg = (const float4*)(x + (size_t)n0 * DD);
        #pragma unroll
        for (int i = 0; i < (BN * DD / 4) / THREADS; i++) {   // 4
            int idx = tid + i * THREADS;
            int n  = idx & (BN - 1);
            int c4 = idx >> 6;            // 0..15, float4 index within row
            float4 v = xg[n * (DD / 4) + c4];
            xs[c4 * 2    ][n] = pack2(v.x, v.y);
            xs[c4 * 2 + 1][n] = pack2(v.z, v.w);
        }
    }
    // ---- load w tile negated: BM x DD = 1024 float4, 4 per thread ----
    {
        const float4* wg = (const float4*)(w + (size_t)m0 * DD);
        #pragma unroll
        for (int i = 0; i < (BM * DD / 4) / THREADS; i++) {   // 4
            int idx = tid + i * THREADS;
            int m  = idx & (BM - 1);
            int c4 = idx >> 6;            // 0..15
            float4 v = wg[m * (DD / 4) + c4];
            ws[c4 * 2    ][m] = pack2(-v.x, -v.y);
            ws[c4 * 2 + 1][m] = pack2(-v.z, -v.w);
        }
    }
    __syncthreads();

    const int tx = tid & 15;   // m group: thread's m values are tx + j*16
    const int ty = tid >> 4;   // n group: thread's n values are ty*4 + i

    ull acc[TN][TM];
    #pragma unroll
    for (int i = 0; i < TN; i++)
        #pragma unroll
        for (int j = 0; j < TM; j++) acc[i][j] = 0ULL;

    #pragma unroll 4
    for (int dp = 0; dp < DP; dp++) {
        ull xr[TN], wr[TM];
        #pragma unroll
        for (int i = 0; i < TN; i++) xr[i] = xs[dp][ty * TN + i];   // 2-addr broadcast
        #pragma unroll
        for (int j = 0; j < TM; j++) wr[j] = ws[dp][j * 16 + tx];   // conflict-free
        #pragma unroll
        for (int i = 0; i < TN; i++)
            #pragma unroll
            for (int j = 0; j < TM; j++)
                l1acc(acc[i][j], xr[i], wr[j]);
    }

    // ---- epilogue: out[n][m] = -(lo + hi) ----
    #pragma unroll
    for (int i = 0; i < TN; i++) {
        const size_t nrow = (size_t)(n0 + ty * TN + i) * (size_t)Mtot;
        #pragma unroll
        for (int j = 0; j < TM; j++) {
            float lo, hi;
            asm("mov.b64 {%0, %1}, %2;" : "=f"(lo), "=f"(hi) : "l"(acc[i][j]));
            out[nrow + m0 + j * 16 + tx] = -(lo + hi);
        }
    }
}

extern "C" void kernel_launch(void* const* d_in, const int* in_sizes, int n_in,
                              void* d_out, int out_size) {
    const float* x = (const float*)d_in[0];   // [N, 64] fp32
    const float* w = (const float*)d_in[1];   // [M, 64] fp32
    float* out = (float*)d_out;               // [N, M] fp32

    const int N = in_sizes[0] / DD;   // 8192
    const int M = in_sizes[1] / DD;   // 1024

    dim3 grid(M / BM, N / BN);        // (16, 128)
    cdist_l1_kernel<<<grid, THREADS>>>(x, w, out, M);
}

// round 3
// speedup vs baseline: 1.1199x; 1.0792x over previous
#include <cuda_runtime.h>

#define BN 64    // n rows per block
#define BM 64    // m cols per block
#define TN 4     // n per thread
#define TM 4     // m per thread
#define DD 64    // feature dim
#define C4 16    // DD/4 float4 chunks
#define THREADS 256

// acc = m * 1.0f + acc  -> FFMA-imm form (rt_SMSP=1, vs FADD rt=2)
__device__ __forceinline__ void ffma_acc1(float &acc, float m) {
    asm("fma.rn.f32 %0, %1, 0f3F800000, %0;" : "+f"(acc) : "f"(m));
}

__global__ __launch_bounds__(THREADS, 4)
void cdist_l1_kernel(const float4* __restrict__ x4,
                     const float4* __restrict__ w4,
                     float* __restrict__ out,
                     int Mtot)
{
    // [d-chunk][row] layout, 16KB each
    __shared__ float4 xs[C4][BN];
    __shared__ float4 ws[C4][BM];
    __shared__ float Sx[BN];   // row sums of x tile
    __shared__ float Sw[BM];   // row sums of w tile

    const int tid = threadIdx.x;
    const int n0 = blockIdx.y * BN;
    const int m0 = blockIdx.x * BM;

    // ---- load tiles: 1024 float4 each, 4 per thread ----
    #pragma unroll
    for (int i = 0; i < (BN * C4) / THREADS; i++) {   // 4
        int idx = tid + i * THREADS;
        int n  = idx & (BN - 1);
        int c  = idx >> 6;
        xs[c][n] = x4[(size_t)(n0 + n) * C4 + c];
    }
    #pragma unroll
    for (int i = 0; i < (BM * C4) / THREADS; i++) {   // 4
        int idx = tid + i * THREADS;
        int m  = idx & (BM - 1);
        int c  = idx >> 6;
        ws[c][m] = w4[(size_t)(m0 + m) * C4 + c];
    }
    __syncthreads();

    // ---- per-row sums (threads 0..127, one-time, ~3% of math) ----
    if (tid < BN) {
        float s = 0.f;
        #pragma unroll
        for (int c = 0; c < C4; c++) {
            float4 v = xs[c][tid];
            s += (v.x + v.y) + (v.z + v.w);
        }
        Sx[tid] = s;
    } else if (tid < BN + BM) {
        int m = tid - BN;
        float s = 0.f;
        #pragma unroll
        for (int c = 0; c < C4; c++) {
            float4 v = ws[c][m];
            s += (v.x + v.y) + (v.z + v.w);
        }
        Sw[m] = s;
    }

    const int tx = tid & 15;   // m: tx + j*16
    const int ty = tid >> 4;   // n: ty*4 + i

    // acc[i][j] accumulates sum_d max(x_d, w_d)
    float acc[TN][TM];
    #pragma unroll
    for (int i = 0; i < TN; i++)
        #pragma unroll
        for (int j = 0; j < TM; j++) acc[i][j] = 0.f;

    #pragma unroll 4
    for (int c = 0; c < C4; c++) {
        float4 xr[TN], wr[TM];
        #pragma unroll
        for (int i = 0; i < TN; i++) xr[i] = xs[c][ty * TN + i];
        #pragma unroll
        for (int j = 0; j < TM; j++) wr[j] = ws[c][j * 16 + tx];
        #pragma unroll
        for (int i = 0; i < TN; i++)
            #pragma unroll
            for (int j = 0; j < TM; j++) {
                ffma_acc1(acc[i][j], fmaxf(xr[i].x, wr[j].x));  // FMNMX (alu) + FFMA-imm
                ffma_acc1(acc[i][j], fmaxf(xr[i].y, wr[j].y));
                ffma_acc1(acc[i][j], fmaxf(xr[i].z, wr[j].z));
                ffma_acc1(acc[i][j], fmaxf(xr[i].w, wr[j].w));
            }
    }

    __syncthreads();   // Sx/Sw written by warps 0-3 before mainloop; make visible

    // ---- epilogue: out[n][m] = Sx[n] + Sw[m] - 2*sum_max ----
    float sxr[TN], swr[TM];
    #pragma unroll
    for (int i = 0; i < TN; i++) sxr[i] = Sx[ty * TN + i];
    #pragma unroll
    for (int j = 0; j < TM; j++) swr[j] = Sw[j * 16 + tx];

    #pragma unroll
    for (int i = 0; i < TN; i++) {
        const size_t nrow = (size_t)(n0 + ty * TN + i) * (size_t)Mtot;
        #pragma unroll
        for (int j = 0; j < TM; j++) {
            out[nrow + m0 + j * 16 + tx] = fmaf(-2.f, acc[i][j], sxr[i] + swr[j]);
        }
    }
}

extern "C" void kernel_launch(void* const* d_in, const int* in_sizes, int n_in,
                              void* d_out, int out_size) {
    const float4* x4 = (const float4*)d_in[0];   // [N, 64] fp32
    const float4* w4 = (const float4*)d_in[1];   // [M, 64] fp32
    float* out = (float*)d_out;                  // [N, M] fp32

    const int N = in_sizes[0] / DD;   // 8192
    const int M = in_sizes[1] / DD;   // 1024

    dim3 grid(M / BM, N / BN);        // (16, 128)
    cdist_l1_kernel<<<grid, THREADS>>>(x4, w4, out, M);
}